// round 12
// baseline (speedup 1.0000x reference)
#include <cuda_runtime.h>

typedef unsigned long long u64;

#define BATCH 8
#define NCH   19
#define HH    512
#define WW    512
#define NWORDS 8                 // 512 cols / 64 bits
#define IMG_WORDS (HH*NWORDS)    // 4096 words per image

// Scratch (device globals — no allocation)
__device__ u64   g_imgp8[BATCH*HH*WW/8];              // 2 MB, u8 pixels packed
__device__ u64   g_strong[2][BATCH*IMG_WORDS];
__device__ u64   g_weak  [2][BATCH*IMG_WORDS];
// TRANSPOSED edge layout: word index = wc*HH + h  (column-major word storage)
__device__ u64   g_edges [2][BATCH*IMG_WORDS];
__device__ float g_loss;
__device__ unsigned g_count;

// ---------------------------------------------------------------------------
// Kernel 1: per-pixel argmax over 19 channels -> img_p = (cls*255)%256 as u8
// 8 pixels (2 float4) per thread; one u64 store. Also resets loss accumulators.
// ---------------------------------------------------------------------------
__global__ __launch_bounds__(256) void argmax_kernel(const float* __restrict__ pred) {
    if (blockIdx.x == 0 && threadIdx.x == 0) { g_loss = 0.0f; g_count = 0u; }
    const int Q = (HH*WW)/4;                 // 65536 float4 per channel plane
    int i = blockIdx.x*256 + threadIdx.x;    // 8*Q/2 threads
    int j = 2*i;
    int b = j / Q;
    int p = j - b*Q;
    const float4* base = reinterpret_cast<const float4*>(pred) + (size_t)b*NCH*Q + p;
    float4 best0 = base[0];
    float4 best1 = base[1];
    int i0x=0,i0y=0,i0z=0,i0w=0, i1x=0,i1y=0,i1z=0,i1w=0;
    #pragma unroll
    for (int c = 1; c < NCH; ++c) {
        float4 v0 = base[(size_t)c*Q];
        float4 v1 = base[(size_t)c*Q + 1];
        if (v0.x > best0.x) { best0.x = v0.x; i0x = c; }
        if (v0.y > best0.y) { best0.y = v0.y; i0y = c; }
        if (v0.z > best0.z) { best0.z = v0.z; i0z = c; }
        if (v0.w > best0.w) { best0.w = v0.w; i0w = c; }
        if (v1.x > best1.x) { best1.x = v1.x; i1x = c; }
        if (v1.y > best1.y) { best1.y = v1.y; i1y = c; }
        if (v1.z > best1.z) { best1.z = v1.z; i1z = c; }
        if (v1.w > best1.w) { best1.w = v1.w; i1w = c; }
    }
    // (cls*255)%256 = cls ? 256-cls : 0, all fit in u8
    u64 w = 0;
    w |= (u64)(unsigned char)(i0x ? 256 - i0x : 0);
    w |= (u64)(unsigned char)(i0y ? 256 - i0y : 0) << 8;
    w |= (u64)(unsigned char)(i0z ? 256 - i0z : 0) << 16;
    w |= (u64)(unsigned char)(i0w ? 256 - i0w : 0) << 24;
    w |= (u64)(unsigned char)(i1x ? 256 - i1x : 0) << 32;
    w |= (u64)(unsigned char)(i1y ? 256 - i1y : 0) << 40;
    w |= (u64)(unsigned char)(i1z ? 256 - i1z : 0) << 48;
    w |= (u64)(unsigned char)(i1w ? 256 - i1w : 0) << 56;
    g_imgp8[i] = w;
}

// ---------------------------------------------------------------------------
// Kernel 2: Canny frontend, integer pipeline, 32x32 tiles (2048 CTAs/image ->
// occupancy no longer grid-limited). u8 image tile, int Sobel, u16 magnitude,
// int NMS/thresholds; only the two angle-bin boundary compares are fp32
// (exactness proven via Pell bound). One warp ballot = one u32 mask half-word.
// ---------------------------------------------------------------------------
__device__ __forceinline__ int binof_i(int gx, int gy) {
    // Exact quantization of atan2 angle mod 180 into {0:d0, 1:d45, 2:d90, 3:d135}
    if (gy == 0) return 0;           // includes gx==0,gy==0 -> angle 0
    if (gx == 0) return 2;           // +-90 deg
    int ax = gx < 0 ? -gx : gx, ay = gy < 0 ? -gy : gy;
    float fax = (float)ax, fay = (float)ay;
    const float T1 = 0.41421356237309503f;   // tan(22.5) = sqrt(2)-1
    if (fay < T1*fax) return 0;               // |angle| < 22.5
    if (T1*fay < fax)                          // < 67.5  (tan67.5 = 1/T1)
        return ((gx > 0) == (gy > 0)) ? 1 : 3;
    return 2;
}

template<int SEL>
__global__ __launch_bounds__(256) void canny_front(const float* __restrict__ labels) {
    __shared__ unsigned char  simg[36][40];   // img tile, halo 2 (edge-clamped)
    __shared__ unsigned short smag[34][40];   // mag tile, halo 1 (0 outside image)
    __shared__ unsigned char  sbin[32][32];
    const int tx0 = blockIdx.x*32, ty0 = blockIdx.y*32;
    const int b = blockIdx.z;
    const int t = threadIdx.x;
    const unsigned char* ip8 =
        reinterpret_cast<const unsigned char*>(g_imgp8) + (size_t)b*HH*WW;
    const float* ipf = labels + (size_t)b*HH*WW;
    // load img tile (edge padding via clamp): 36x36
    for (int i = t; i < 36*36; i += 256) {
        int r = i / 36, c = i - r*36;         // /36 -> mul-shift (const)
        int gy = ty0 + r - 2; gy = gy < 0 ? 0 : (gy > HH-1 ? HH-1 : gy);
        int gx = tx0 + c - 2; gx = gx < 0 ? 0 : (gx > WW-1 ? WW-1 : gx);
        unsigned char v;
        if (SEL == 0) v = ip8[gy*WW + gx];
        else          v = (unsigned char)(int)floorf(ipf[gy*WW + gx] * 255.0f);
        simg[r][c] = v;
    }
    __syncthreads();
    // mag (+bin for centers), integer Sobel; mag = 0 outside the image: 34x34
    for (int i = t; i < 34*34; i += 256) {
        int r = i / 34, c = i - r*34;
        int gy = ty0 + r - 1, gx = tx0 + c - 1;
        int m = 0;
        if ((unsigned)gy < (unsigned)HH && (unsigned)gx < (unsigned)WW) {
            int a00=simg[r][c],   a01=simg[r][c+1],   a02=simg[r][c+2];
            int a10=simg[r+1][c],                     a12=simg[r+1][c+2];
            int a20=simg[r+2][c], a21=simg[r+2][c+1], a22=simg[r+2][c+2];
            int gxv = (a02 - a00) + 2*(a12 - a10) + (a22 - a20);
            int gyv = (a20 - a00) + 2*(a21 - a01) + (a22 - a02);
            int axv = gxv < 0 ? -gxv : gxv;
            int ayv = gyv < 0 ? -gyv : gyv;
            m = axv + ayv;                     // <= 2040, fits u16
            if (r >= 1 && r < 33 && c >= 1 && c < 33)
                sbin[r-1][c-1] = (unsigned char)binof_i(gxv, gyv);
        }
        smag[r][c] = (unsigned short)m;
    }
    __syncthreads();
    // NMS + thresholds (all int); one warp ballot = 32-px row mask (u32 store)
    const int warp = t >> 5, lane = t & 31;
    unsigned* gs32 = reinterpret_cast<unsigned*>(g_strong[SEL]);
    unsigned* gw32 = reinterpret_cast<unsigned*>(g_weak[SEL]);
    for (int r = warp; r < 32; r += 8) {
        int m = smag[r+1][lane+1];
        int bn = sbin[r][lane];
        int n1, n2;
        if      (bn == 0) { n1 = smag[r+1][lane+2]; n2 = smag[r+1][lane];   }
        else if (bn == 1) { n1 = smag[r][lane+2];   n2 = smag[r+2][lane];   }
        else if (bn == 2) { n1 = smag[r+2][lane+1]; n2 = smag[r][lane+1];   }
        else              { n1 = smag[r][lane];     n2 = smag[r+2][lane+2]; }
        bool keep = (m >= n1) && (m >= n2);
        unsigned sm = __ballot_sync(0xffffffffu, keep && (m > 200));
        unsigned wm = __ballot_sync(0xffffffffu, keep && (m > 100));
        if (lane == 0) {
            // u32 view: row stride = 16 u32 words; blockIdx.x in [0,16)
            size_t w = ((size_t)b*HH + (ty0 + r))*(2*NWORDS) + blockIdx.x;
            gs32[w] = sm;
            gw32[w] = wm;
        }
    }
}

// ---------------------------------------------------------------------------
// Kernel 3: hysteresis to fixed point (cap 256), whole image in smem, bitpacked
// One image set per launch (IMG template param), grid = 8 CTAs, 512 threads.
// Final edges stored TRANSPOSED: word index wc*HH + h (coalesced loss staging).
// ---------------------------------------------------------------------------
template<int IMG>
__global__ __launch_bounds__(512) void hyst_kernel() {
    extern __shared__ u64 sh[];
    u64* s  = sh;              // 4096 words: current state
    u64* hd = sh + IMG_WORDS;  // 4096 words: horizontal dilation
    const int b = blockIdx.x;
    const u64* wbase = g_weak[IMG]   + (size_t)b*IMG_WORDS;
    const u64* sbase = g_strong[IMG] + (size_t)b*IMG_WORDS;
    const int t = threadIdx.x;
    u64 wr[8];
    #pragma unroll
    for (int k = 0; k < 8; ++k) {
        int idx = t + 512*k;
        wr[k] = wbase[idx];
        s[idx] = sbase[idx];
    }
    __syncthreads();
    bool changed = true;
    for (int it = 0; it < 256 && changed; ++it) {
        #pragma unroll
        for (int k = 0; k < 8; ++k) {
            int idx = t + 512*k;
            int wc = idx & 7;
            u64 x = s[idx];
            u64 l = wc       ? s[idx-1] : 0ull;
            u64 r = (wc < 7) ? s[idx+1] : 0ull;
            hd[idx] = x | (x << 1) | (x >> 1) | (l >> 63) | (r << 63);
        }
        __syncthreads();
        int my = 0;
        #pragma unroll
        for (int k = 0; k < 8; ++k) {
            int idx = t + 512*k;
            int h = idx >> 3;
            u64 v = hd[idx];
            if (h > 0)      v |= hd[idx - 8];
            if (h < HH-1)   v |= hd[idx + 8];
            v &= wr[k];
            my |= (int)(v != s[idx]);
            s[idx] = v;
        }
        changed = (__syncthreads_or(my) != 0);
    }
    // store transposed: (h, wc) -> wc*HH + h
    #pragma unroll
    for (int k = 0; k < 8; ++k) {
        int idx = t + 512*k;
        int h = idx >> 3, wc = idx & 7;
        g_edges[IMG][(size_t)b*IMG_WORDS + wc*HH + h] = s[idx];
    }
}

// ---------------------------------------------------------------------------
// Kernel 4: closed-form loss. Per (b,w) column over H:
//   n1p = sum ep, S_el = sum el; S_both via flat popcount.
//   loss = [ sum_col S_el*log(512 + n1p*(e-1)) - sum popc(ep&el) ]/4096
// One CTA per (batch, word-column), 1024 threads. Coalesced staging
// (transposed edges); extraction via conflict-free broadcast LDS.
// ---------------------------------------------------------------------------
__global__ __launch_bounds__(1024) void loss_kernel(float* __restrict__ out) {
    __shared__ u64 sep[HH];     // pred edge column words
    __shared__ u64 slb[HH];     // label edge column words
    __shared__ int ssb[16];     // per-warp popc(ep&el) partials
    const int b  = blockIdx.x >> 3;
    const int wc = blockIdx.x & 7;
    const int t  = threadIdx.x;
    const u64* __restrict__ ep = g_edges[0] + (size_t)b*IMG_WORDS + wc*HH;
    const u64* __restrict__ el = g_edges[1] + (size_t)b*IMG_WORDS + wc*HH;
    // stage (coalesced) + flat popcount of ep&el
    int sb = 0;
    if (t < 512) {
        u64 A = __ldg(ep + t);
        u64 B = __ldg(el + t);
        sep[t] = A;
        slb[t] = B;
        sb = __popcll(A & B);
        #pragma unroll
        for (int o = 16; o; o >>= 1) sb += __shfl_down_sync(0xffffffffu, sb, o);
        if ((t & 31) == 0) ssb[t >> 5] = sb;
    }
    __syncthreads();
    const int bit   = t >> 4;    // 0..63
    const int chunk = t & 15;    // strided row subset
    int n1p = 0, selc = 0;
    #pragma unroll
    for (int i = 0; i < 32; ++i) {
        int h = chunk + 16*i;    // lanes 0-15 hit 16 consecutive u64s: no conflicts
        n1p  += (int)((sep[h] >> bit) & 1ull);
        selc += (int)((slb[h] >> bit) & 1ull);
    }
    // combine 16 row-chunks of the same bit (adjacent lanes)
    #pragma unroll
    for (int o = 8; o; o >>= 1) {
        n1p  += __shfl_down_sync(0xffffffffu, n1p,  o, 16);
        selc += __shfl_down_sync(0xffffffffu, selc, o, 16);
    }
    float val = 0.0f;
    if (chunk == 0) {
        const float EM1 = 1.7182818284590452f;    // e - 1
        float lse = logf(512.0f + (float)n1p * EM1);
        val = (float)selc * lse;
    }
    // warp + block reduce, one atomic per block
    #pragma unroll
    for (int o = 16; o; o >>= 1) val += __shfl_down_sync(0xffffffffu, val, o);
    __shared__ float wsum[32];
    if ((t & 31) == 0) wsum[t >> 5] = val;
    __syncthreads();
    if (t < 32) {
        float v = wsum[t];
        #pragma unroll
        for (int o = 16; o; o >>= 1) v += __shfl_down_sync(0xffffffffu, v, o);
        if (t == 0) {
            int stot = 0;
            #pragma unroll
            for (int i = 0; i < 16; ++i) stot += ssb[i];
            atomicAdd(&g_loss, (v - (float)stot) * (1.0f/4096.0f));
        }
    }
    // last block finalizes the scalar output
    if (t == 0) {
        __threadfence();
        unsigned prev = atomicAdd(&g_count, 1u);
        if (prev == gridDim.x - 1) {
            out[0] = atomicAdd(&g_loss, 0.0f);  // atomic read: coherent with adds
        }
    }
}

// ---------------------------------------------------------------------------
extern "C" void kernel_launch(void* const* d_in, const int* in_sizes, int n_in,
                              void* d_out, int out_size) {
    const float* pred   = (const float*)d_in[0];
    const float* labels = (const float*)d_in[1];
    // defensive: identify by size (pred has 19x more elements)
    if (n_in >= 2 && in_sizes[0] == BATCH*HH*WW) {
        const float* tmp = pred; pred = labels; labels = tmp;
    }

    // one-time host-side setup (streams/events are host objects, not device mem)
    static cudaStream_t s2 = nullptr;
    static cudaEvent_t evFork = nullptr, evJoin = nullptr;
    static bool smem_set = false;
    if (!s2) {
        cudaStreamCreateWithFlags(&s2, cudaStreamNonBlocking);
        cudaEventCreateWithFlags(&evFork, cudaEventDisableTiming);
        cudaEventCreateWithFlags(&evJoin, cudaEventDisableTiming);
    }
    if (!smem_set) {
        cudaFuncSetAttribute(hyst_kernel<0>, cudaFuncAttributeMaxDynamicSharedMemorySize,
                             2*IMG_WORDS*(int)sizeof(u64));
        cudaFuncSetAttribute(hyst_kernel<1>, cudaFuncAttributeMaxDynamicSharedMemorySize,
                             2*IMG_WORDS*(int)sizeof(u64));
        smem_set = true;
    }

    dim3 g(WW/32, HH/32, BATCH);   // 32x32 tiles -> 2048 CTAs per image

    // fork: label pipeline on s2 (independent of argmax)
    cudaEventRecord(evFork, 0);
    cudaStreamWaitEvent(s2, evFork, 0);
    canny_front<1><<<g, 256, 0, s2>>>(labels);
    hyst_kernel<1><<<BATCH, 512, 2*IMG_WORDS*sizeof(u64), s2>>>();
    cudaEventRecord(evJoin, s2);

    // pred pipeline on default stream
    argmax_kernel<<<(BATCH*((HH*WW)/4)/2)/256, 256>>>(pred);
    canny_front<0><<<g, 256>>>(nullptr);
    hyst_kernel<0><<<BATCH, 512, 2*IMG_WORDS*sizeof(u64)>>>();

    // join, then loss
    cudaStreamWaitEvent(0, evJoin, 0);
    loss_kernel<<<64, 1024>>>((float*)d_out);
}

// round 14
// speedup vs baseline: 1.0877x; 1.0877x over previous
#include <cuda_runtime.h>

typedef unsigned long long u64;

#define BATCH 8
#define NCH   19
#define HH    512
#define WW    512
#define NWORDS 8                 // 512 cols / 64 bits
#define IMG_WORDS (HH*NWORDS)    // 4096 words per image

// Scratch (device globals — no allocation)
__device__ u64   g_imgp8[BATCH*HH*WW/8];              // 2 MB, u8 pixels packed
__device__ u64   g_strong[2][BATCH*IMG_WORDS];
__device__ u64   g_weak  [2][BATCH*IMG_WORDS];
// TRANSPOSED edge layout: word index = wc*HH + h  (column-major word storage)
__device__ u64   g_edges [2][BATCH*IMG_WORDS];
__device__ float g_loss;
__device__ unsigned g_count;

// ---------------------------------------------------------------------------
// Kernel 1: per-pixel argmax over 19 channels for ONE batch image.
// 8 pixels (2 float4) per thread; one u64 store. grid=128 CTAs.
// ---------------------------------------------------------------------------
__global__ __launch_bounds__(256) void argmax_kernel(const float* __restrict__ pred,
                                                     int b) {
    if (b == 0 && blockIdx.x == 0 && threadIdx.x == 0) { g_loss = 0.0f; g_count = 0u; }
    const int Q = (HH*WW)/4;                 // 65536 float4 per channel plane
    int i = blockIdx.x*256 + threadIdx.x;    // 0..32767
    int p = 2*i;
    const float4* base = reinterpret_cast<const float4*>(pred) + (size_t)b*NCH*Q + p;
    float4 best0 = base[0];
    float4 best1 = base[1];
    int i0x=0,i0y=0,i0z=0,i0w=0, i1x=0,i1y=0,i1z=0,i1w=0;
    #pragma unroll
    for (int c = 1; c < NCH; ++c) {
        float4 v0 = base[(size_t)c*Q];
        float4 v1 = base[(size_t)c*Q + 1];
        if (v0.x > best0.x) { best0.x = v0.x; i0x = c; }
        if (v0.y > best0.y) { best0.y = v0.y; i0y = c; }
        if (v0.z > best0.z) { best0.z = v0.z; i0z = c; }
        if (v0.w > best0.w) { best0.w = v0.w; i0w = c; }
        if (v1.x > best1.x) { best1.x = v1.x; i1x = c; }
        if (v1.y > best1.y) { best1.y = v1.y; i1y = c; }
        if (v1.z > best1.z) { best1.z = v1.z; i1z = c; }
        if (v1.w > best1.w) { best1.w = v1.w; i1w = c; }
    }
    // (cls*255)%256 = cls ? 256-cls : 0, all fit in u8
    u64 w = 0;
    w |= (u64)(unsigned char)(i0x ? 256 - i0x : 0);
    w |= (u64)(unsigned char)(i0y ? 256 - i0y : 0) << 8;
    w |= (u64)(unsigned char)(i0z ? 256 - i0z : 0) << 16;
    w |= (u64)(unsigned char)(i0w ? 256 - i0w : 0) << 24;
    w |= (u64)(unsigned char)(i1x ? 256 - i1x : 0) << 32;
    w |= (u64)(unsigned char)(i1y ? 256 - i1y : 0) << 40;
    w |= (u64)(unsigned char)(i1z ? 256 - i1z : 0) << 48;
    w |= (u64)(unsigned char)(i1w ? 256 - i1w : 0) << 56;
    g_imgp8[(size_t)b*(HH*WW/8) + i] = w;
}

// ---------------------------------------------------------------------------
// Kernel 2: Canny frontend, integer pipeline, 32x32 tiles. b = b0 + blockIdx.z
// (pred path launches per-batch with grid z=1; label path z=8).
// ---------------------------------------------------------------------------
__device__ __forceinline__ int binof_i(int gx, int gy) {
    // Exact quantization of atan2 angle mod 180 into {0:d0, 1:d45, 2:d90, 3:d135}
    if (gy == 0) return 0;           // includes gx==0,gy==0 -> angle 0
    if (gx == 0) return 2;           // +-90 deg
    int ax = gx < 0 ? -gx : gx, ay = gy < 0 ? -gy : gy;
    float fax = (float)ax, fay = (float)ay;
    const float T1 = 0.41421356237309503f;   // tan(22.5) = sqrt(2)-1
    if (fay < T1*fax) return 0;               // |angle| < 22.5
    if (T1*fay < fax)                          // < 67.5  (tan67.5 = 1/T1)
        return ((gx > 0) == (gy > 0)) ? 1 : 3;
    return 2;
}

template<int SEL>
__global__ __launch_bounds__(256) void canny_front(const float* __restrict__ labels,
                                                   int b0) {
    __shared__ unsigned char  simg[36][40];   // img tile, halo 2 (edge-clamped)
    __shared__ unsigned short smag[34][40];   // mag tile, halo 1 (0 outside image)
    __shared__ unsigned char  sbin[32][32];
    const int tx0 = blockIdx.x*32, ty0 = blockIdx.y*32;
    const int b = b0 + blockIdx.z;
    const int t = threadIdx.x;
    const unsigned char* ip8 =
        reinterpret_cast<const unsigned char*>(g_imgp8) + (size_t)b*HH*WW;
    const float* ipf = labels + (size_t)b*HH*WW;
    // load img tile (edge padding via clamp): 36x36
    for (int i = t; i < 36*36; i += 256) {
        int r = i / 36, c = i - r*36;
        int gy = ty0 + r - 2; gy = gy < 0 ? 0 : (gy > HH-1 ? HH-1 : gy);
        int gx = tx0 + c - 2; gx = gx < 0 ? 0 : (gx > WW-1 ? WW-1 : gx);
        unsigned char v;
        if (SEL == 0) v = ip8[gy*WW + gx];
        else          v = (unsigned char)(int)floorf(ipf[gy*WW + gx] * 255.0f);
        simg[r][c] = v;
    }
    __syncthreads();
    // mag (+bin for centers), integer Sobel; mag = 0 outside the image: 34x34
    for (int i = t; i < 34*34; i += 256) {
        int r = i / 34, c = i - r*34;
        int gy = ty0 + r - 1, gx = tx0 + c - 1;
        int m = 0;
        if ((unsigned)gy < (unsigned)HH && (unsigned)gx < (unsigned)WW) {
            int a00=simg[r][c],   a01=simg[r][c+1],   a02=simg[r][c+2];
            int a10=simg[r+1][c],                     a12=simg[r+1][c+2];
            int a20=simg[r+2][c], a21=simg[r+2][c+1], a22=simg[r+2][c+2];
            int gxv = (a02 - a00) + 2*(a12 - a10) + (a22 - a20);
            int gyv = (a20 - a00) + 2*(a21 - a01) + (a22 - a02);
            int axv = gxv < 0 ? -gxv : gxv;
            int ayv = gyv < 0 ? -gyv : gyv;
            m = axv + ayv;                     // <= 2040, fits u16
            if (r >= 1 && r < 33 && c >= 1 && c < 33)
                sbin[r-1][c-1] = (unsigned char)binof_i(gxv, gyv);
        }
        smag[r][c] = (unsigned short)m;
    }
    __syncthreads();
    // NMS + thresholds (all int); one warp ballot = 32-px row mask (u32 store)
    const int warp = t >> 5, lane = t & 31;
    unsigned* gs32 = reinterpret_cast<unsigned*>(g_strong[SEL]);
    unsigned* gw32 = reinterpret_cast<unsigned*>(g_weak[SEL]);
    for (int r = warp; r < 32; r += 8) {
        int m = smag[r+1][lane+1];
        int bn = sbin[r][lane];
        int n1, n2;
        if      (bn == 0) { n1 = smag[r+1][lane+2]; n2 = smag[r+1][lane];   }
        else if (bn == 1) { n1 = smag[r][lane+2];   n2 = smag[r+2][lane];   }
        else if (bn == 2) { n1 = smag[r+2][lane+1]; n2 = smag[r][lane+1];   }
        else              { n1 = smag[r][lane];     n2 = smag[r+2][lane+2]; }
        bool keep = (m >= n1) && (m >= n2);
        unsigned sm = __ballot_sync(0xffffffffu, keep && (m > 200));
        unsigned wm = __ballot_sync(0xffffffffu, keep && (m > 100));
        if (lane == 0) {
            // u32 view: row stride = 16 u32 words; blockIdx.x in [0,16)
            size_t w = ((size_t)b*HH + (ty0 + r))*(2*NWORDS) + blockIdx.x;
            gs32[w] = sm;
            gw32[w] = wm;
        }
    }
}

// ---------------------------------------------------------------------------
// Kernel 3: hysteresis to fixed point (cap 256), whole image in smem, bitpacked
// b = b0 + blockIdx.x, 512 threads, 64KB dynamic smem.
// Final edges stored TRANSPOSED: word index wc*HH + h (coalesced loss staging).
// ---------------------------------------------------------------------------
template<int IMG>
__global__ __launch_bounds__(512) void hyst_kernel(int b0) {
    extern __shared__ u64 sh[];
    u64* s  = sh;              // 4096 words: current state
    u64* hd = sh + IMG_WORDS;  // 4096 words: horizontal dilation
    const int b = b0 + blockIdx.x;
    const u64* wbase = g_weak[IMG]   + (size_t)b*IMG_WORDS;
    const u64* sbase = g_strong[IMG] + (size_t)b*IMG_WORDS;
    const int t = threadIdx.x;
    u64 wr[8];
    #pragma unroll
    for (int k = 0; k < 8; ++k) {
        int idx = t + 512*k;
        wr[k] = wbase[idx];
        s[idx] = sbase[idx];
    }
    __syncthreads();
    bool changed = true;
    for (int it = 0; it < 256 && changed; ++it) {
        #pragma unroll
        for (int k = 0; k < 8; ++k) {
            int idx = t + 512*k;
            int wc = idx & 7;
            u64 x = s[idx];
            u64 l = wc       ? s[idx-1] : 0ull;
            u64 r = (wc < 7) ? s[idx+1] : 0ull;
            hd[idx] = x | (x << 1) | (x >> 1) | (l >> 63) | (r << 63);
        }
        __syncthreads();
        int my = 0;
        #pragma unroll
        for (int k = 0; k < 8; ++k) {
            int idx = t + 512*k;
            int h = idx >> 3;
            u64 v = hd[idx];
            if (h > 0)      v |= hd[idx - 8];
            if (h < HH-1)   v |= hd[idx + 8];
            v &= wr[k];
            my |= (int)(v != s[idx]);
            s[idx] = v;
        }
        changed = (__syncthreads_or(my) != 0);
    }
    // store transposed: (h, wc) -> wc*HH + h
    #pragma unroll
    for (int k = 0; k < 8; ++k) {
        int idx = t + 512*k;
        int h = idx >> 3, wc = idx & 7;
        g_edges[IMG][(size_t)b*IMG_WORDS + wc*HH + h] = s[idx];
    }
}

// ---------------------------------------------------------------------------
// Kernel 4: closed-form loss. Per (b,w) column over H:
//   n1p = sum ep, S_el = sum el; S_both via flat popcount.
//   loss = [ sum_col S_el*log(512 + n1p*(e-1)) - sum popc(ep&el) ]/4096
// One CTA per (batch, word-column), 1024 threads. Coalesced staging
// (transposed edges); extraction via conflict-free broadcast LDS.
// ---------------------------------------------------------------------------
__global__ __launch_bounds__(1024) void loss_kernel(float* __restrict__ out) {
    __shared__ u64 sep[HH];     // pred edge column words
    __shared__ u64 slb[HH];     // label edge column words
    __shared__ int ssb[16];     // per-warp popc(ep&el) partials
    const int b  = blockIdx.x >> 3;
    const int wc = blockIdx.x & 7;
    const int t  = threadIdx.x;
    const u64* __restrict__ ep = g_edges[0] + (size_t)b*IMG_WORDS + wc*HH;
    const u64* __restrict__ el = g_edges[1] + (size_t)b*IMG_WORDS + wc*HH;
    // stage (coalesced) + flat popcount of ep&el
    int sb = 0;
    if (t < 512) {
        u64 A = __ldg(ep + t);
        u64 B = __ldg(el + t);
        sep[t] = A;
        slb[t] = B;
        sb = __popcll(A & B);
        #pragma unroll
        for (int o = 16; o; o >>= 1) sb += __shfl_down_sync(0xffffffffu, sb, o);
        if ((t & 31) == 0) ssb[t >> 5] = sb;
    }
    __syncthreads();
    const int bit   = t >> 4;    // 0..63
    const int chunk = t & 15;    // strided row subset
    int n1p = 0, selc = 0;
    #pragma unroll
    for (int i = 0; i < 32; ++i) {
        int h = chunk + 16*i;    // lanes 0-15 hit 16 consecutive u64s: no conflicts
        n1p  += (int)((sep[h] >> bit) & 1ull);
        selc += (int)((slb[h] >> bit) & 1ull);
    }
    // combine 16 row-chunks of the same bit (adjacent lanes)
    #pragma unroll
    for (int o = 8; o; o >>= 1) {
        n1p  += __shfl_down_sync(0xffffffffu, n1p,  o, 16);
        selc += __shfl_down_sync(0xffffffffu, selc, o, 16);
    }
    float val = 0.0f;
    if (chunk == 0) {
        const float EM1 = 1.7182818284590452f;    // e - 1
        float lse = logf(512.0f + (float)n1p * EM1);
        val = (float)selc * lse;
    }
    // warp + block reduce, one atomic per block
    #pragma unroll
    for (int o = 16; o; o >>= 1) val += __shfl_down_sync(0xffffffffu, val, o);
    __shared__ float wsum[32];
    if ((t & 31) == 0) wsum[t >> 5] = val;
    __syncthreads();
    if (t < 32) {
        float v = wsum[t];
        #pragma unroll
        for (int o = 16; o; o >>= 1) v += __shfl_down_sync(0xffffffffu, v, o);
        if (t == 0) {
            int stot = 0;
            #pragma unroll
            for (int i = 0; i < 16; ++i) stot += ssb[i];
            atomicAdd(&g_loss, (v - (float)stot) * (1.0f/4096.0f));
        }
    }
    // last block finalizes the scalar output
    if (t == 0) {
        __threadfence();
        unsigned prev = atomicAdd(&g_count, 1u);
        if (prev == gridDim.x - 1) {
            out[0] = atomicAdd(&g_loss, 0.0f);  // atomic read: coherent with adds
        }
    }
}

// ---------------------------------------------------------------------------
extern "C" void kernel_launch(void* const* d_in, const int* in_sizes, int n_in,
                              void* d_out, int out_size) {
    const float* pred   = (const float*)d_in[0];
    const float* labels = (const float*)d_in[1];
    // defensive: identify by size (pred has 19x more elements)
    if (n_in >= 2 && in_sizes[0] == BATCH*HH*WW) {
        const float* tmp = pred; pred = labels; labels = tmp;
    }

    // one-time host-side setup: exactly 2 created streams (pool-safe; 9 streams
    // tripped the harness's device-memory guard via a driver pool grow)
    static cudaStream_t sW = nullptr;       // pred worker stream
    static cudaStream_t sL = nullptr;       // label stream
    static cudaEvent_t evFork = nullptr;
    static cudaEvent_t eA[BATCH] = {};      // argmax(b) done
    static cudaEvent_t eJ0 = nullptr, eJ1 = nullptr;
    static bool init_done = false;
    if (!init_done) {
        cudaStreamCreateWithFlags(&sW, cudaStreamNonBlocking);
        cudaStreamCreateWithFlags(&sL, cudaStreamNonBlocking);
        cudaEventCreateWithFlags(&evFork, cudaEventDisableTiming);
        for (int b = 0; b < BATCH; ++b)
            cudaEventCreateWithFlags(&eA[b], cudaEventDisableTiming);
        cudaEventCreateWithFlags(&eJ0, cudaEventDisableTiming);
        cudaEventCreateWithFlags(&eJ1, cudaEventDisableTiming);
        cudaFuncSetAttribute(hyst_kernel<0>, cudaFuncAttributeMaxDynamicSharedMemorySize,
                             2*IMG_WORDS*(int)sizeof(u64));
        cudaFuncSetAttribute(hyst_kernel<1>, cudaFuncAttributeMaxDynamicSharedMemorySize,
                             2*IMG_WORDS*(int)sizeof(u64));
        init_done = true;
    }

    // fork: label pipeline (independent of pred entirely)
    cudaEventRecord(evFork, 0);
    cudaStreamWaitEvent(sL, evFork, 0);
    {
        dim3 gl(WW/32, HH/32, BATCH);
        canny_front<1><<<gl, 256, 0, sL>>>(labels, 0);
        hyst_kernel<1><<<BATCH, 512, 2*IMG_WORDS*sizeof(u64), sL>>>(0);
        cudaEventRecord(eJ1, sL);
    }

    // pred pipeline, batch-pipelined: argmax(b) on stream 0; canny0(b) on the
    // worker stream gated by eA[b] (each canny0(b) is ~3us; serialization on
    // one stream stays hidden behind argmax). hyst0 runs once over all 8
    // batches (8 concurrent CTAs) after the last canny.
    dim3 gp(WW/32, HH/32, 1);
    for (int b = 0; b < BATCH; ++b) {
        argmax_kernel<<<128, 256>>>(pred, b);
        cudaEventRecord(eA[b], 0);
        cudaStreamWaitEvent(sW, eA[b], 0);
        canny_front<0><<<gp, 256, 0, sW>>>(nullptr, b);
    }
    hyst_kernel<0><<<BATCH, 512, 2*IMG_WORDS*sizeof(u64), sW>>>(0);
    cudaEventRecord(eJ0, sW);

    // join both side streams into origin, then loss
    cudaStreamWaitEvent(0, eJ0, 0);
    cudaStreamWaitEvent(0, eJ1, 0);
    loss_kernel<<<64, 1024>>>((float*)d_out);
}

// round 15
// speedup vs baseline: 1.3936x; 1.2813x over previous
#include <cuda_runtime.h>

typedef unsigned long long u64;

#define BATCH 8
#define NCH   19
#define HH    512
#define WW    512
#define HW    (HH*WW)
#define NWORDS 8                 // 512 cols / 64 bits
#define IMG_WORDS (HH*NWORDS)    // 4096 words per image

// Scratch (device globals — no allocation)
__device__ u64   g_strong[2][BATCH*IMG_WORDS];
__device__ u64   g_weak  [2][BATCH*IMG_WORDS];
// TRANSPOSED edge layout: word index = wc*HH + h  (column-major word storage)
__device__ u64   g_edges [2][BATCH*IMG_WORDS];
__device__ float g_loss;
__device__ unsigned g_count;

// ---------------------------------------------------------------------------
// Canny core pieces (shared by both frontends)
// ---------------------------------------------------------------------------
__device__ __forceinline__ int binof_i(int gx, int gy) {
    // Exact quantization of atan2 angle mod 180 into {0:d0, 1:d45, 2:d90, 3:d135}
    if (gy == 0) return 0;           // includes gx==0,gy==0 -> angle 0
    if (gx == 0) return 2;           // +-90 deg
    int ax = gx < 0 ? -gx : gx, ay = gy < 0 ? -gy : gy;
    float fax = (float)ax, fay = (float)ay;
    const float T1 = 0.41421356237309503f;   // tan(22.5) = sqrt(2)-1
    if (fay < T1*fax) return 0;               // |angle| < 22.5
    if (T1*fay < fax)                          // < 67.5  (tan67.5 = 1/T1)
        return ((gx > 0) == (gy > 0)) ? 1 : 3;
    return 2;
}

// Sobel + NMS + thresholds from a filled simg tile; writes bitpacked masks.
template<int SEL>
__device__ __forceinline__ void canny_core(
    unsigned char (&simg)[36][40], unsigned short (&smag)[34][40],
    unsigned char (&sbin)[32][32], int tx0, int ty0, int b, int t, int bx)
{
    // mag (+bin for centers), integer Sobel; mag = 0 outside the image: 34x34
    for (int i = t; i < 34*34; i += 256) {
        int r = i / 34, c = i - r*34;
        int gy = ty0 + r - 1, gx = tx0 + c - 1;
        int m = 0;
        if ((unsigned)gy < (unsigned)HH && (unsigned)gx < (unsigned)WW) {
            int a00=simg[r][c],   a01=simg[r][c+1],   a02=simg[r][c+2];
            int a10=simg[r+1][c],                     a12=simg[r+1][c+2];
            int a20=simg[r+2][c], a21=simg[r+2][c+1], a22=simg[r+2][c+2];
            int gxv = (a02 - a00) + 2*(a12 - a10) + (a22 - a20);
            int gyv = (a20 - a00) + 2*(a21 - a01) + (a22 - a02);
            int axv = gxv < 0 ? -gxv : gxv;
            int ayv = gyv < 0 ? -gyv : gyv;
            m = axv + ayv;                     // <= 2040, fits u16
            if (r >= 1 && r < 33 && c >= 1 && c < 33)
                sbin[r-1][c-1] = (unsigned char)binof_i(gxv, gyv);
        }
        smag[r][c] = (unsigned short)m;
    }
    __syncthreads();
    // NMS + thresholds (all int); one warp ballot = 32-px row mask (u32 store)
    const int warp = t >> 5, lane = t & 31;
    unsigned* gs32 = reinterpret_cast<unsigned*>(g_strong[SEL]);
    unsigned* gw32 = reinterpret_cast<unsigned*>(g_weak[SEL]);
    for (int r = warp; r < 32; r += 8) {
        int m = smag[r+1][lane+1];
        int bn = sbin[r][lane];
        int n1, n2;
        if      (bn == 0) { n1 = smag[r+1][lane+2]; n2 = smag[r+1][lane];   }
        else if (bn == 1) { n1 = smag[r][lane+2];   n2 = smag[r+2][lane];   }
        else if (bn == 2) { n1 = smag[r+2][lane+1]; n2 = smag[r][lane+1];   }
        else              { n1 = smag[r][lane];     n2 = smag[r+2][lane+2]; }
        bool keep = (m >= n1) && (m >= n2);
        unsigned sm = __ballot_sync(0xffffffffu, keep && (m > 200));
        unsigned wm = __ballot_sync(0xffffffffu, keep && (m > 100));
        if (lane == 0) {
            // u32 view: row stride = 16 u32 words; bx in [0,16)
            size_t w = ((size_t)b*HH + (ty0 + r))*(2*NWORDS) + bx;
            gs32[w] = sm;
            gw32[w] = wm;
        }
    }
}

// ---------------------------------------------------------------------------
// Kernel A: FUSED argmax + Canny for the pred image. One CTA per 32x32 tile;
// each CTA computes channel-argmax directly from pred for its 36x36 halo tile
// (no imgp8 round-trip, no serial argmax stage). 2048 CTAs.
// ---------------------------------------------------------------------------
__global__ __launch_bounds__(256) void canny_pred(const float* __restrict__ pred) {
    __shared__ unsigned char  simg[36][40];
    __shared__ unsigned short smag[34][40];
    __shared__ unsigned char  sbin[32][32];
    const int tx0 = blockIdx.x*32, ty0 = blockIdx.y*32;
    const int b = blockIdx.z;
    const int t = threadIdx.x;
    const float* base = pred + (size_t)b*NCH*HW;
    // load tile: per-pixel argmax over 19 channels (edge-clamped coords)
    for (int i = t; i < 36*36; i += 256) {
        int r = i / 36, c = i - r*36;
        int gy = ty0 + r - 2; gy = gy < 0 ? 0 : (gy > HH-1 ? HH-1 : gy);
        int gx = tx0 + c - 2; gx = gx < 0 ? 0 : (gx > WW-1 ? WW-1 : gx);
        const float* pp = base + gy*WW + gx;
        float best = __ldg(pp);
        int bi = 0;
        #pragma unroll
        for (int ch = 1; ch < NCH; ++ch) {
            float v = __ldg(pp + (size_t)ch*HW);
            if (v > best) { best = v; bi = ch; }
        }
        // (cls*255)%256 = cls ? 256-cls : 0
        simg[r][c] = (unsigned char)(bi ? 256 - bi : 0);
    }
    __syncthreads();
    canny_core<0>(simg, smag, sbin, tx0, ty0, b, t, blockIdx.x);
}

// ---------------------------------------------------------------------------
// Kernel B: Canny for the label image (floor(l*255) as u8). 2048 CTAs.
// ---------------------------------------------------------------------------
__global__ __launch_bounds__(256) void canny_lbl(const float* __restrict__ labels) {
    __shared__ unsigned char  simg[36][40];
    __shared__ unsigned short smag[34][40];
    __shared__ unsigned char  sbin[32][32];
    const int tx0 = blockIdx.x*32, ty0 = blockIdx.y*32;
    const int b = blockIdx.z;
    const int t = threadIdx.x;
    const float* ipf = labels + (size_t)b*HW;
    for (int i = t; i < 36*36; i += 256) {
        int r = i / 36, c = i - r*36;
        int gy = ty0 + r - 2; gy = gy < 0 ? 0 : (gy > HH-1 ? HH-1 : gy);
        int gx = tx0 + c - 2; gx = gx < 0 ? 0 : (gx > WW-1 ? WW-1 : gx);
        simg[r][c] = (unsigned char)(int)floorf(__ldg(ipf + gy*WW + gx) * 255.0f);
    }
    __syncthreads();
    canny_core<1>(simg, smag, sbin, tx0, ty0, b, t, blockIdx.x);
}

// ---------------------------------------------------------------------------
// Kernel 3: hysteresis to fixed point (cap 256), whole image in smem, bitpacked
// grid = 8 CTAs (one per batch), 512 threads, 64KB dynamic smem.
// Also (idempotently) resets the loss accumulators — both hyst launches
// complete before loss runs, and both write the same zeros.
// Final edges stored TRANSPOSED: word index wc*HH + h (coalesced loss staging).
// ---------------------------------------------------------------------------
template<int IMG>
__global__ __launch_bounds__(512) void hyst_kernel() {
    if (blockIdx.x == 0 && threadIdx.x == 0) { g_loss = 0.0f; g_count = 0u; }
    extern __shared__ u64 sh[];
    u64* s  = sh;              // 4096 words: current state
    u64* hd = sh + IMG_WORDS;  // 4096 words: horizontal dilation
    const int b = blockIdx.x;
    const u64* wbase = g_weak[IMG]   + (size_t)b*IMG_WORDS;
    const u64* sbase = g_strong[IMG] + (size_t)b*IMG_WORDS;
    const int t = threadIdx.x;
    u64 wr[8];
    #pragma unroll
    for (int k = 0; k < 8; ++k) {
        int idx = t + 512*k;
        wr[k] = wbase[idx];
        s[idx] = sbase[idx];
    }
    __syncthreads();
    bool changed = true;
    for (int it = 0; it < 256 && changed; ++it) {
        #pragma unroll
        for (int k = 0; k < 8; ++k) {
            int idx = t + 512*k;
            int wc = idx & 7;
            u64 x = s[idx];
            u64 l = wc       ? s[idx-1] : 0ull;
            u64 r = (wc < 7) ? s[idx+1] : 0ull;
            hd[idx] = x | (x << 1) | (x >> 1) | (l >> 63) | (r << 63);
        }
        __syncthreads();
        int my = 0;
        #pragma unroll
        for (int k = 0; k < 8; ++k) {
            int idx = t + 512*k;
            int h = idx >> 3;
            u64 v = hd[idx];
            if (h > 0)      v |= hd[idx - 8];
            if (h < HH-1)   v |= hd[idx + 8];
            v &= wr[k];
            my |= (int)(v != s[idx]);
            s[idx] = v;
        }
        changed = (__syncthreads_or(my) != 0);
    }
    // store transposed: (h, wc) -> wc*HH + h
    #pragma unroll
    for (int k = 0; k < 8; ++k) {
        int idx = t + 512*k;
        int h = idx >> 3, wc = idx & 7;
        g_edges[IMG][(size_t)b*IMG_WORDS + wc*HH + h] = s[idx];
    }
}

// ---------------------------------------------------------------------------
// Kernel 4: closed-form loss. Per (b,w) column over H:
//   n1p = sum ep, S_el = sum el; S_both via flat popcount.
//   loss = [ sum_col S_el*log(512 + n1p*(e-1)) - sum popc(ep&el) ]/4096
// One CTA per (batch, word-column), 1024 threads. Coalesced staging
// (transposed edges); extraction via conflict-free broadcast LDS.
// ---------------------------------------------------------------------------
__global__ __launch_bounds__(1024) void loss_kernel(float* __restrict__ out) {
    __shared__ u64 sep[HH];     // pred edge column words
    __shared__ u64 slb[HH];     // label edge column words
    __shared__ int ssb[16];     // per-warp popc(ep&el) partials
    const int b  = blockIdx.x >> 3;
    const int wc = blockIdx.x & 7;
    const int t  = threadIdx.x;
    const u64* __restrict__ ep = g_edges[0] + (size_t)b*IMG_WORDS + wc*HH;
    const u64* __restrict__ el = g_edges[1] + (size_t)b*IMG_WORDS + wc*HH;
    // stage (coalesced) + flat popcount of ep&el
    int sb = 0;
    if (t < 512) {
        u64 A = __ldg(ep + t);
        u64 B = __ldg(el + t);
        sep[t] = A;
        slb[t] = B;
        sb = __popcll(A & B);
        #pragma unroll
        for (int o = 16; o; o >>= 1) sb += __shfl_down_sync(0xffffffffu, sb, o);
        if ((t & 31) == 0) ssb[t >> 5] = sb;
    }
    __syncthreads();
    const int bit   = t >> 4;    // 0..63
    const int chunk = t & 15;    // strided row subset
    int n1p = 0, selc = 0;
    #pragma unroll
    for (int i = 0; i < 32; ++i) {
        int h = chunk + 16*i;    // lanes 0-15 hit 16 consecutive u64s: no conflicts
        n1p  += (int)((sep[h] >> bit) & 1ull);
        selc += (int)((slb[h] >> bit) & 1ull);
    }
    // combine 16 row-chunks of the same bit (adjacent lanes)
    #pragma unroll
    for (int o = 8; o; o >>= 1) {
        n1p  += __shfl_down_sync(0xffffffffu, n1p,  o, 16);
        selc += __shfl_down_sync(0xffffffffu, selc, o, 16);
    }
    float val = 0.0f;
    if (chunk == 0) {
        const float EM1 = 1.7182818284590452f;    // e - 1
        float lse = logf(512.0f + (float)n1p * EM1);
        val = (float)selc * lse;
    }
    // warp + block reduce, one atomic per block
    #pragma unroll
    for (int o = 16; o; o >>= 1) val += __shfl_down_sync(0xffffffffu, val, o);
    __shared__ float wsum[32];
    if ((t & 31) == 0) wsum[t >> 5] = val;
    __syncthreads();
    if (t < 32) {
        float v = wsum[t];
        #pragma unroll
        for (int o = 16; o; o >>= 1) v += __shfl_down_sync(0xffffffffu, v, o);
        if (t == 0) {
            int stot = 0;
            #pragma unroll
            for (int i = 0; i < 16; ++i) stot += ssb[i];
            atomicAdd(&g_loss, (v - (float)stot) * (1.0f/4096.0f));
        }
    }
    // last block finalizes the scalar output
    if (t == 0) {
        __threadfence();
        unsigned prev = atomicAdd(&g_count, 1u);
        if (prev == gridDim.x - 1) {
            out[0] = atomicAdd(&g_loss, 0.0f);  // atomic read: coherent with adds
        }
    }
}

// ---------------------------------------------------------------------------
extern "C" void kernel_launch(void* const* d_in, const int* in_sizes, int n_in,
                              void* d_out, int out_size) {
    const float* pred   = (const float*)d_in[0];
    const float* labels = (const float*)d_in[1];
    // defensive: identify by size (pred has 19x more elements)
    if (n_in >= 2 && in_sizes[0] == BATCH*HH*WW) {
        const float* tmp = pred; pred = labels; labels = tmp;
    }

    // one-time host-side setup: 1 created stream + 2 events (mem-guard-safe)
    static cudaStream_t sL = nullptr;
    static cudaEvent_t evFork = nullptr, evJoin = nullptr;
    static bool init_done = false;
    if (!init_done) {
        cudaStreamCreateWithFlags(&sL, cudaStreamNonBlocking);
        cudaEventCreateWithFlags(&evFork, cudaEventDisableTiming);
        cudaEventCreateWithFlags(&evJoin, cudaEventDisableTiming);
        cudaFuncSetAttribute(hyst_kernel<0>, cudaFuncAttributeMaxDynamicSharedMemorySize,
                             2*IMG_WORDS*(int)sizeof(u64));
        cudaFuncSetAttribute(hyst_kernel<1>, cudaFuncAttributeMaxDynamicSharedMemorySize,
                             2*IMG_WORDS*(int)sizeof(u64));
        init_done = true;
    }

    dim3 g(WW/32, HH/32, BATCH);

    // fork: label pipeline on sL (fully independent of pred path)
    cudaEventRecord(evFork, 0);
    cudaStreamWaitEvent(sL, evFork, 0);
    canny_lbl<<<g, 256, 0, sL>>>(labels);
    hyst_kernel<1><<<BATCH, 512, 2*IMG_WORDS*sizeof(u64), sL>>>();
    cudaEventRecord(evJoin, sL);

    // pred path on stream 0: fused argmax+canny, then hysteresis
    canny_pred<<<g, 256>>>(pred);
    hyst_kernel<0><<<BATCH, 512, 2*IMG_WORDS*sizeof(u64)>>>();

    // join, then loss
    cudaStreamWaitEvent(0, evJoin, 0);
    loss_kernel<<<64, 1024>>>((float*)d_out);
}

// round 16
// speedup vs baseline: 1.4123x; 1.0134x over previous
#include <cuda_runtime.h>

typedef unsigned long long u64;

#define BATCH 8
#define NCH   19
#define HH    512
#define WW    512
#define HW    (HH*WW)
#define NWORDS 8                 // 512 cols / 64 bits
#define IMG_WORDS (HH*NWORDS)    // 4096 words per image

// Scratch (device globals — no allocation)
__device__ u64   g_strong[2][BATCH*IMG_WORDS];
__device__ u64   g_weak  [2][BATCH*IMG_WORDS];
// TRANSPOSED edge layout: word index = wc*HH + h  (column-major word storage)
__device__ u64   g_edges [2][BATCH*IMG_WORDS];
__device__ float g_loss;
__device__ unsigned g_count;

// ---------------------------------------------------------------------------
// Canny core pieces (shared by both frontends)
// ---------------------------------------------------------------------------
__device__ __forceinline__ int binof_i(int gx, int gy) {
    // Exact quantization of atan2 angle mod 180 into {0:d0, 1:d45, 2:d90, 3:d135}
    if (gy == 0) return 0;           // includes gx==0,gy==0 -> angle 0
    if (gx == 0) return 2;           // +-90 deg
    int ax = gx < 0 ? -gx : gx, ay = gy < 0 ? -gy : gy;
    float fax = (float)ax, fay = (float)ay;
    const float T1 = 0.41421356237309503f;   // tan(22.5) = sqrt(2)-1
    if (fay < T1*fax) return 0;               // |angle| < 22.5
    if (T1*fay < fax)                          // < 67.5  (tan67.5 = 1/T1)
        return ((gx > 0) == (gy > 0)) ? 1 : 3;
    return 2;
}

// Sobel + NMS + thresholds from a filled simg tile; writes bitpacked masks.
template<int SEL>
__device__ __forceinline__ void canny_core(
    unsigned char (&simg)[36][40], unsigned short (&smag)[34][40],
    unsigned char (&sbin)[32][32], int tx0, int ty0, int b, int t, int bx)
{
    // mag (+bin for centers), integer Sobel; mag = 0 outside the image: 34x34
    for (int i = t; i < 34*34; i += 256) {
        int r = i / 34, c = i - r*34;
        int gy = ty0 + r - 1, gx = tx0 + c - 1;
        int m = 0;
        if ((unsigned)gy < (unsigned)HH && (unsigned)gx < (unsigned)WW) {
            int a00=simg[r][c],   a01=simg[r][c+1],   a02=simg[r][c+2];
            int a10=simg[r+1][c],                     a12=simg[r+1][c+2];
            int a20=simg[r+2][c], a21=simg[r+2][c+1], a22=simg[r+2][c+2];
            int gxv = (a02 - a00) + 2*(a12 - a10) + (a22 - a20);
            int gyv = (a20 - a00) + 2*(a21 - a01) + (a22 - a02);
            int axv = gxv < 0 ? -gxv : gxv;
            int ayv = gyv < 0 ? -gyv : gyv;
            m = axv + ayv;                     // <= 2040, fits u16
            if (r >= 1 && r < 33 && c >= 1 && c < 33)
                sbin[r-1][c-1] = (unsigned char)binof_i(gxv, gyv);
        }
        smag[r][c] = (unsigned short)m;
    }
    __syncthreads();
    // NMS + thresholds (all int); one warp ballot = 32-px row mask (u32 store)
    const int warp = t >> 5, lane = t & 31;
    unsigned* gs32 = reinterpret_cast<unsigned*>(g_strong[SEL]);
    unsigned* gw32 = reinterpret_cast<unsigned*>(g_weak[SEL]);
    for (int r = warp; r < 32; r += 8) {
        int m = smag[r+1][lane+1];
        int bn = sbin[r][lane];
        int n1, n2;
        if      (bn == 0) { n1 = smag[r+1][lane+2]; n2 = smag[r+1][lane];   }
        else if (bn == 1) { n1 = smag[r][lane+2];   n2 = smag[r+2][lane];   }
        else if (bn == 2) { n1 = smag[r+2][lane+1]; n2 = smag[r][lane+1];   }
        else              { n1 = smag[r][lane];     n2 = smag[r+2][lane+2]; }
        bool keep = (m >= n1) && (m >= n2);
        unsigned sm = __ballot_sync(0xffffffffu, keep && (m > 200));
        unsigned wm = __ballot_sync(0xffffffffu, keep && (m > 100));
        if (lane == 0) {
            // u32 view: row stride = 16 u32 words; bx in [0,16)
            size_t w = ((size_t)b*HH + (ty0 + r))*(2*NWORDS) + bx;
            gs32[w] = sm;
            gw32[w] = wm;
        }
    }
}

// ---------------------------------------------------------------------------
// Kernel A: FUSED argmax + Canny for the pred image, float4 argmax loads.
// One CTA per 32x32 tile; halo row span [tx0-4, tx0+36) = 10 aligned float4
// groups x 36 rows = 360 groups. Interior groups: LDG.128 x 19 channels with
// 4-lane running argmax. Border groups: clamped scalar fallback. 2048 CTAs.
// ---------------------------------------------------------------------------
__global__ __launch_bounds__(256) void canny_pred(const float* __restrict__ pred) {
    __shared__ unsigned char  simg[36][40];
    __shared__ unsigned short smag[34][40];
    __shared__ unsigned char  sbin[32][32];
    const int tx0 = blockIdx.x*32, ty0 = blockIdx.y*32;
    const int b = blockIdx.z;
    const int t = threadIdx.x;
    const float* base = pred + (size_t)b*NCH*HW;
    for (int i = t; i < 360; i += 256) {
        int r = i / 10, g = i - r*10;
        int gy = ty0 + r - 2; gy = gy < 0 ? 0 : (gy > HH-1 ? HH-1 : gy);
        int gx0 = tx0 - 4 + 4*g;             // 16B-aligned column base
        int cbase = 4*g - 2;                 // tile-local column of lane 0
        if (gx0 >= 0 && gx0 + 3 < WW) {
            const float4* pp = reinterpret_cast<const float4*>(base + gy*WW + gx0);
            float4 best = pp[0];
            int ix = 0, iy = 0, iz = 0, iw = 0;
            #pragma unroll
            for (int ch = 1; ch < NCH; ++ch) {
                float4 v = pp[(size_t)ch*(HW/4)];
                if (v.x > best.x) { best.x = v.x; ix = ch; }
                if (v.y > best.y) { best.y = v.y; iy = ch; }
                if (v.z > best.z) { best.z = v.z; iz = ch; }
                if (v.w > best.w) { best.w = v.w; iw = ch; }
            }
            unsigned char vals[4];
            vals[0] = (unsigned char)(ix ? 256 - ix : 0);
            vals[1] = (unsigned char)(iy ? 256 - iy : 0);
            vals[2] = (unsigned char)(iz ? 256 - iz : 0);
            vals[3] = (unsigned char)(iw ? 256 - iw : 0);
            #pragma unroll
            for (int k = 0; k < 4; ++k) {
                int c = cbase + k;
                if ((unsigned)c < 36u) simg[r][c] = vals[k];
            }
        } else {
            // border group: per-lane clamped scalar argmax
            #pragma unroll
            for (int k = 0; k < 4; ++k) {
                int c = cbase + k;
                if ((unsigned)c < 36u) {
                    int gx = gx0 + k; gx = gx < 0 ? 0 : (gx > WW-1 ? WW-1 : gx);
                    const float* pp = base + gy*WW + gx;
                    float bestv = __ldg(pp);
                    int bi = 0;
                    #pragma unroll
                    for (int ch = 1; ch < NCH; ++ch) {
                        float v = __ldg(pp + (size_t)ch*HW);
                        if (v > bestv) { bestv = v; bi = ch; }
                    }
                    simg[r][c] = (unsigned char)(bi ? 256 - bi : 0);
                }
            }
        }
    }
    __syncthreads();
    canny_core<0>(simg, smag, sbin, tx0, ty0, b, t, blockIdx.x);
}

// ---------------------------------------------------------------------------
// Kernel B: Canny for the label image (floor(l*255) as u8). 2048 CTAs.
// ---------------------------------------------------------------------------
__global__ __launch_bounds__(256) void canny_lbl(const float* __restrict__ labels) {
    __shared__ unsigned char  simg[36][40];
    __shared__ unsigned short smag[34][40];
    __shared__ unsigned char  sbin[32][32];
    const int tx0 = blockIdx.x*32, ty0 = blockIdx.y*32;
    const int b = blockIdx.z;
    const int t = threadIdx.x;
    const float* ipf = labels + (size_t)b*HW;
    for (int i = t; i < 36*36; i += 256) {
        int r = i / 36, c = i - r*36;
        int gy = ty0 + r - 2; gy = gy < 0 ? 0 : (gy > HH-1 ? HH-1 : gy);
        int gx = tx0 + c - 2; gx = gx < 0 ? 0 : (gx > WW-1 ? WW-1 : gx);
        simg[r][c] = (unsigned char)(int)floorf(__ldg(ipf + gy*WW + gx) * 255.0f);
    }
    __syncthreads();
    canny_core<1>(simg, smag, sbin, tx0, ty0, b, t, blockIdx.x);
}

// ---------------------------------------------------------------------------
// Kernel 3: hysteresis to fixed point (cap 256), whole image in smem, bitpacked
// grid = 8 CTAs (one per batch), 512 threads, 64KB dynamic smem.
// Also (idempotently) resets the loss accumulators — both hyst launches
// complete before loss runs, and both write the same zeros.
// Final edges stored TRANSPOSED: word index wc*HH + h (coalesced loss staging).
// ---------------------------------------------------------------------------
template<int IMG>
__global__ __launch_bounds__(512) void hyst_kernel() {
    if (blockIdx.x == 0 && threadIdx.x == 0) { g_loss = 0.0f; g_count = 0u; }
    extern __shared__ u64 sh[];
    u64* s  = sh;              // 4096 words: current state
    u64* hd = sh + IMG_WORDS;  // 4096 words: horizontal dilation
    const int b = blockIdx.x;
    const u64* wbase = g_weak[IMG]   + (size_t)b*IMG_WORDS;
    const u64* sbase = g_strong[IMG] + (size_t)b*IMG_WORDS;
    const int t = threadIdx.x;
    u64 wr[8];
    #pragma unroll
    for (int k = 0; k < 8; ++k) {
        int idx = t + 512*k;
        wr[k] = wbase[idx];
        s[idx] = sbase[idx];
    }
    __syncthreads();
    bool changed = true;
    for (int it = 0; it < 256 && changed; ++it) {
        #pragma unroll
        for (int k = 0; k < 8; ++k) {
            int idx = t + 512*k;
            int wc = idx & 7;
            u64 x = s[idx];
            u64 l = wc       ? s[idx-1] : 0ull;
            u64 r = (wc < 7) ? s[idx+1] : 0ull;
            hd[idx] = x | (x << 1) | (x >> 1) | (l >> 63) | (r << 63);
        }
        __syncthreads();
        int my = 0;
        #pragma unroll
        for (int k = 0; k < 8; ++k) {
            int idx = t + 512*k;
            int h = idx >> 3;
            u64 v = hd[idx];
            if (h > 0)      v |= hd[idx - 8];
            if (h < HH-1)   v |= hd[idx + 8];
            v &= wr[k];
            my |= (int)(v != s[idx]);
            s[idx] = v;
        }
        changed = (__syncthreads_or(my) != 0);
    }
    // store transposed: (h, wc) -> wc*HH + h
    #pragma unroll
    for (int k = 0; k < 8; ++k) {
        int idx = t + 512*k;
        int h = idx >> 3, wc = idx & 7;
        g_edges[IMG][(size_t)b*IMG_WORDS + wc*HH + h] = s[idx];
    }
}

// ---------------------------------------------------------------------------
// Kernel 4: closed-form loss. Per (b,w) column over H:
//   n1p = sum ep, S_el = sum el; S_both via flat popcount.
//   loss = [ sum_col S_el*log(512 + n1p*(e-1)) - sum popc(ep&el) ]/4096
// One CTA per (batch, word-column), 1024 threads. Coalesced staging
// (transposed edges); extraction via conflict-free broadcast LDS.
// ---------------------------------------------------------------------------
__global__ __launch_bounds__(1024) void loss_kernel(float* __restrict__ out) {
    __shared__ u64 sep[HH];     // pred edge column words
    __shared__ u64 slb[HH];     // label edge column words
    __shared__ int ssb[16];     // per-warp popc(ep&el) partials
    const int b  = blockIdx.x >> 3;
    const int wc = blockIdx.x & 7;
    const int t  = threadIdx.x;
    const u64* __restrict__ ep = g_edges[0] + (size_t)b*IMG_WORDS + wc*HH;
    const u64* __restrict__ el = g_edges[1] + (size_t)b*IMG_WORDS + wc*HH;
    // stage (coalesced) + flat popcount of ep&el
    int sb = 0;
    if (t < 512) {
        u64 A = __ldg(ep + t);
        u64 B = __ldg(el + t);
        sep[t] = A;
        slb[t] = B;
        sb = __popcll(A & B);
        #pragma unroll
        for (int o = 16; o; o >>= 1) sb += __shfl_down_sync(0xffffffffu, sb, o);
        if ((t & 31) == 0) ssb[t >> 5] = sb;
    }
    __syncthreads();
    const int bit   = t >> 4;    // 0..63
    const int chunk = t & 15;    // strided row subset
    int n1p = 0, selc = 0;
    #pragma unroll
    for (int i = 0; i < 32; ++i) {
        int h = chunk + 16*i;    // lanes 0-15 hit 16 consecutive u64s: no conflicts
        n1p  += (int)((sep[h] >> bit) & 1ull);
        selc += (int)((slb[h] >> bit) & 1ull);
    }
    // combine 16 row-chunks of the same bit (adjacent lanes)
    #pragma unroll
    for (int o = 8; o; o >>= 1) {
        n1p  += __shfl_down_sync(0xffffffffu, n1p,  o, 16);
        selc += __shfl_down_sync(0xffffffffu, selc, o, 16);
    }
    float val = 0.0f;
    if (chunk == 0) {
        const float EM1 = 1.7182818284590452f;    // e - 1
        float lse = logf(512.0f + (float)n1p * EM1);
        val = (float)selc * lse;
    }
    // warp + block reduce, one atomic per block
    #pragma unroll
    for (int o = 16; o; o >>= 1) val += __shfl_down_sync(0xffffffffu, val, o);
    __shared__ float wsum[32];
    if ((t & 31) == 0) wsum[t >> 5] = val;
    __syncthreads();
    if (t < 32) {
        float v = wsum[t];
        #pragma unroll
        for (int o = 16; o; o >>= 1) v += __shfl_down_sync(0xffffffffu, v, o);
        if (t == 0) {
            int stot = 0;
            #pragma unroll
            for (int i = 0; i < 16; ++i) stot += ssb[i];
            atomicAdd(&g_loss, (v - (float)stot) * (1.0f/4096.0f));
        }
    }
    // last block finalizes the scalar output
    if (t == 0) {
        __threadfence();
        unsigned prev = atomicAdd(&g_count, 1u);
        if (prev == gridDim.x - 1) {
            out[0] = atomicAdd(&g_loss, 0.0f);  // atomic read: coherent with adds
        }
    }
}

// ---------------------------------------------------------------------------
extern "C" void kernel_launch(void* const* d_in, const int* in_sizes, int n_in,
                              void* d_out, int out_size) {
    const float* pred   = (const float*)d_in[0];
    const float* labels = (const float*)d_in[1];
    // defensive: identify by size (pred has 19x more elements)
    if (n_in >= 2 && in_sizes[0] == BATCH*HH*WW) {
        const float* tmp = pred; pred = labels; labels = tmp;
    }

    // one-time host-side setup: 1 created stream + 2 events (mem-guard-safe)
    static cudaStream_t sL = nullptr;
    static cudaEvent_t evFork = nullptr, evJoin = nullptr;
    static bool init_done = false;
    if (!init_done) {
        cudaStreamCreateWithFlags(&sL, cudaStreamNonBlocking);
        cudaEventCreateWithFlags(&evFork, cudaEventDisableTiming);
        cudaEventCreateWithFlags(&evJoin, cudaEventDisableTiming);
        cudaFuncSetAttribute(hyst_kernel<0>, cudaFuncAttributeMaxDynamicSharedMemorySize,
                             2*IMG_WORDS*(int)sizeof(u64));
        cudaFuncSetAttribute(hyst_kernel<1>, cudaFuncAttributeMaxDynamicSharedMemorySize,
                             2*IMG_WORDS*(int)sizeof(u64));
        init_done = true;
    }

    dim3 g(WW/32, HH/32, BATCH);

    // fork event BEFORE any stream-0 kernel so the label path doesn't wait on
    // canny_pred; canny_pred enqueued first so ncu (-s 5 -c 1) captures it.
    cudaEventRecord(evFork, 0);
    canny_pred<<<g, 256>>>(pred);                       // launch 1 (stream 0)
    cudaStreamWaitEvent(sL, evFork, 0);
    canny_lbl<<<g, 256, 0, sL>>>(labels);               // launch 2 (sL)
    hyst_kernel<1><<<BATCH, 512, 2*IMG_WORDS*sizeof(u64), sL>>>();  // launch 3
    cudaEventRecord(evJoin, sL);
    hyst_kernel<0><<<BATCH, 512, 2*IMG_WORDS*sizeof(u64)>>>();      // launch 4
    cudaStreamWaitEvent(0, evJoin, 0);
    loss_kernel<<<64, 1024>>>((float*)d_out);           // launch 5
}